// round 9
// baseline (speedup 1.0000x reference)
#include <cuda_runtime.h>

#define NN 50000
#define NE 1600000
// per-head dims: IN=128, OUT=32, H=4  -> 128 floats of Wh per node

// ---- scratch (static device globals; no allocation) ----
__device__ float g_Wh[NN * 128];     // [n][h][o], h*32+o contiguous
__device__ float g_ssrc[NN * 4];     // per-node src attention score per head
__device__ float g_sdst[NN * 4];     // per-node dst attention score per head
__device__ float g_max[NN * 4];      // segment max per (dst, head)
__device__ float g_sum[NN * 4];      // segment sum of exp per (dst, head)

// ---------------------------------------------------------------------------
__global__ void init_kernel() {
    int i = blockIdx.x * blockDim.x + threadIdx.x;
    if (i < NN * 4) {
        g_max[i] = __int_as_float(0xff800000);  // -inf
        g_sum[i] = 0.0f;
    }
}

// ---------------------------------------------------------------------------
// Wh = x @ W per head, fused with per-node score computation.
// One warp per node. lane -> (h = lane>>3, o-group = (lane&7)*4).
// Note h*32 + (lane&7)*4 == lane*4, so each lane owns float4 at lane*4.
__global__ void wh_kernel(const float* __restrict__ x,
                          const float* __restrict__ W,
                          const float* __restrict__ attn) {
    __shared__ float xs[4][128];
    int warp = threadIdx.x >> 5;
    int lane = threadIdx.x & 31;
    int node = blockIdx.x * 4 + warp;
    if (node >= NN) return;

    // cooperative load of x row (128 floats) into smem
    float4 xv = reinterpret_cast<const float4*>(x + (size_t)node * 128)[lane];
    reinterpret_cast<float4*>(xs[warp])[lane] = xv;
    __syncwarp();

    int h  = lane >> 3;
    int og = (lane & 7) << 2;
    const float4* W4 = reinterpret_cast<const float4*>(W + h * 128 * 32 + og);

    float4 acc = make_float4(0.f, 0.f, 0.f, 0.f);
#pragma unroll 16
    for (int i = 0; i < 128; i++) {
        float  xi = xs[warp][i];
        float4 wv = __ldg(&W4[i * 8]);   // row stride 32 floats = 8 float4
        acc.x = fmaf(xi, wv.x, acc.x);
        acc.y = fmaf(xi, wv.y, acc.y);
        acc.z = fmaf(xi, wv.z, acc.z);
        acc.w = fmaf(xi, wv.w, acc.w);
    }
    reinterpret_cast<float4*>(g_Wh + (size_t)node * 128)[lane] = acc;

    // per-node attention scores: s_src = Wh . a_src, s_dst = Wh . a_dst
    const float* asrc = attn + h * 64 + og;      // attn[h][0:32]
    const float* adst = asrc + 32;               // attn[h][32:64]
    float ps = acc.x * asrc[0] + acc.y * asrc[1] + acc.z * asrc[2] + acc.w * asrc[3];
    float pd = acc.x * adst[0] + acc.y * adst[1] + acc.z * adst[2] + acc.w * adst[3];
    // reduce across the 8 lanes of this head
    ps += __shfl_xor_sync(0xffffffffu, ps, 1);
    ps += __shfl_xor_sync(0xffffffffu, ps, 2);
    ps += __shfl_xor_sync(0xffffffffu, ps, 4);
    pd += __shfl_xor_sync(0xffffffffu, pd, 1);
    pd += __shfl_xor_sync(0xffffffffu, pd, 2);
    pd += __shfl_xor_sync(0xffffffffu, pd, 4);
    if ((lane & 7) == 0) {
        g_ssrc[node * 4 + h] = ps;
        g_sdst[node * 4 + h] = pd;
    }
}

// ---------------------------------------------------------------------------
__device__ __forceinline__ void atomicMaxF(float* a, float v) {
    // monotone-toward-max under mixed races; init must be -inf (0xff800000)
    if (v >= 0.0f) atomicMax(reinterpret_cast<int*>(a), __float_as_int(v));
    else           atomicMin(reinterpret_cast<unsigned int*>(a), __float_as_uint(v));
}

__device__ __forceinline__ void edge_scores(int s, int d, float v[4]) {
    float4 vs = *reinterpret_cast<const float4*>(g_ssrc + (size_t)s * 4);
    float4 vd = *reinterpret_cast<const float4*>(g_sdst + (size_t)d * 4);
    v[0] = vs.x + vd.x; v[1] = vs.y + vd.y; v[2] = vs.z + vd.z; v[3] = vs.w + vd.w;
#pragma unroll
    for (int h = 0; h < 4; h++) v[h] = v[h] > 0.f ? v[h] : 0.2f * v[h];  // leaky_relu
}

// edge_index is int32 on device (JAX default x64-disabled downcasts int64->int32)
__global__ void pass_a(const int2* __restrict__ ei) {
    int e = blockIdx.x * blockDim.x + threadIdx.x;
    if (e >= NE) return;
    int2 sd = __ldg(&ei[e]);
    int s = sd.x, d = sd.y;
    float v[4];
    edge_scores(s, d, v);
#pragma unroll
    for (int h = 0; h < 4; h++) atomicMaxF(&g_max[(size_t)d * 4 + h], v[h]);
}

__global__ void pass_b(const int2* __restrict__ ei, float* __restrict__ alpha) {
    int e = blockIdx.x * blockDim.x + threadIdx.x;
    if (e >= NE) return;
    int2 sd = __ldg(&ei[e]);
    int s = sd.x, d = sd.y;
    float v[4];
    edge_scores(s, d, v);
    float4 m = *reinterpret_cast<const float4*>(g_max + (size_t)d * 4);
    float4 ex;
    ex.x = __expf(v[0] - m.x);
    ex.y = __expf(v[1] - m.y);
    ex.z = __expf(v[2] - m.z);
    ex.w = __expf(v[3] - m.w);
    reinterpret_cast<float4*>(alpha)[e] = ex;  // stash un-normalized exp in alpha slot
    atomicAdd(&g_sum[(size_t)d * 4 + 0], ex.x);
    atomicAdd(&g_sum[(size_t)d * 4 + 1], ex.y);
    atomicAdd(&g_sum[(size_t)d * 4 + 2], ex.z);
    atomicAdd(&g_sum[(size_t)d * 4 + 3], ex.w);
}

// ---------------------------------------------------------------------------
// Pass C: warp per edge. Normalize alpha, gather Wh[src], vector-red into out[dst].
__global__ void pass_c(const int2* __restrict__ ei,
                       float* __restrict__ out_h,
                       float* __restrict__ alpha) {
    int e    = blockIdx.x * 8 + (threadIdx.x >> 5);
    int lane = threadIdx.x & 31;
    if (e >= NE) return;

    int s = 0, d = 0;
    float exl = 0.f;
    if (lane < 4) {
        // lane 0-3: each loads one head's un-normalized exp
        exl = alpha[(size_t)e * 4 + lane];
    }
    if (lane == 0) {
        int2 sd = __ldg(&ei[e]);
        s = sd.x; d = sd.y;
    }
    s = __shfl_sync(0xffffffffu, s, 0);
    d = __shfl_sync(0xffffffffu, d, 0);

    int h = lane >> 3;
    float ex  = __shfl_sync(0xffffffffu, exl, h);          // broadcast head's exp
    float sum = g_sum[(size_t)d * 4 + h];
    float a   = ex / (sum + 1e-9f);
    if ((lane & 7) == 0) alpha[(size_t)e * 4 + h] = a;     // finalize alpha output

    float4 wv = reinterpret_cast<const float4*>(g_Wh + (size_t)s * 128)[lane];
    float rx = a * wv.x, ry = a * wv.y, rz = a * wv.z, rw = a * wv.w;
    float* dst = out_h + (size_t)d * 128 + lane * 4;
    asm volatile("red.global.add.v4.f32 [%0], {%1, %2, %3, %4};"
                 :: "l"(dst), "f"(rx), "f"(ry), "f"(rz), "f"(rw) : "memory");
}

// ---------------------------------------------------------------------------
extern "C" void kernel_launch(void* const* d_in, const int* in_sizes, int n_in,
                              void* d_out, int out_size) {
    const float* x    = (const float*)d_in[0];
    const int2*  ei   = (const int2*)d_in[1];            // [E][2] int32
    const float* W    = (const float*)d_in[2];           // [4][128][32]
    const float* attn = (const float*)d_in[3];           // [4][64]
    float* out   = (float*)d_out;                        // h: [NN][128]
    float* alpha = out + (size_t)NN * 128;               // alpha: [NE][4]

    cudaMemsetAsync(out, 0, (size_t)NN * 128 * sizeof(float), 0);
    init_kernel<<<(NN * 4 + 255) / 256, 256>>>();
    wh_kernel<<<(NN + 3) / 4, 128>>>(x, W, attn);
    pass_a<<<(NE + 255) / 256, 256>>>(ei);
    pass_b<<<(NE + 255) / 256, 256>>>(ei, alpha);
    pass_c<<<NE / 8, 256>>>(ei, out, alpha);
}

// round 13
// speedup vs baseline: 1.5389x; 1.5389x over previous
#include <cuda_runtime.h>

#define NN 50000
#define NE 1600000
#define NB 49          // ceil(NN / 1024)

// ---- scratch (static device globals; no allocation) ----
__device__ float g_Wh[NN * 128];       // [n][h*32+o]
__device__ float g_ssrc[NN * 4];       // per-node src score per head
__device__ float g_sdst[NN * 4];       // per-node dst score per head
__device__ int   g_deg[NN];
__device__ int   g_rowstart[NN + 1];
__device__ int   g_cursor[NN];
__device__ int2  g_csr[NE];            // (src, edge_id) grouped by dst
__device__ int   g_bsum[NB];

// ---------------------------------------------------------------------------
__global__ void k_init() {
    int i = blockIdx.x * blockDim.x + threadIdx.x;
    if (i < NN) g_deg[i] = 0;
}

// ---------------------------------------------------------------------------
// Wh = x @ W per head, fused with per-node score computation. One warp/node.
__global__ void wh_kernel(const float* __restrict__ x,
                          const float* __restrict__ W,
                          const float* __restrict__ attn) {
    __shared__ float xs[4][128];
    int warp = threadIdx.x >> 5;
    int lane = threadIdx.x & 31;
    int node = blockIdx.x * 4 + warp;
    if (node >= NN) return;

    float4 xv = reinterpret_cast<const float4*>(x + (size_t)node * 128)[lane];
    reinterpret_cast<float4*>(xs[warp])[lane] = xv;
    __syncwarp();

    int h  = lane >> 3;
    int og = (lane & 7) << 2;
    const float4* W4 = reinterpret_cast<const float4*>(W + h * 128 * 32 + og);

    float4 acc = make_float4(0.f, 0.f, 0.f, 0.f);
#pragma unroll 16
    for (int i = 0; i < 128; i++) {
        float  xi = xs[warp][i];
        float4 wv = __ldg(&W4[i * 8]);
        acc.x = fmaf(xi, wv.x, acc.x);
        acc.y = fmaf(xi, wv.y, acc.y);
        acc.z = fmaf(xi, wv.z, acc.z);
        acc.w = fmaf(xi, wv.w, acc.w);
    }
    reinterpret_cast<float4*>(g_Wh + (size_t)node * 128)[lane] = acc;

    const float* asrc = attn + h * 64 + og;
    const float* adst = asrc + 32;
    float ps = acc.x * asrc[0] + acc.y * asrc[1] + acc.z * asrc[2] + acc.w * asrc[3];
    float pd = acc.x * adst[0] + acc.y * adst[1] + acc.z * adst[2] + acc.w * adst[3];
    ps += __shfl_xor_sync(0xffffffffu, ps, 1);
    ps += __shfl_xor_sync(0xffffffffu, ps, 2);
    ps += __shfl_xor_sync(0xffffffffu, ps, 4);
    pd += __shfl_xor_sync(0xffffffffu, pd, 1);
    pd += __shfl_xor_sync(0xffffffffu, pd, 2);
    pd += __shfl_xor_sync(0xffffffffu, pd, 4);
    if ((lane & 7) == 0) {
        g_ssrc[node * 4 + h] = ps;
        g_sdst[node * 4 + h] = pd;
    }
}

// ---------------------------------------------------------------------------
// CSR build: count -> scan (3 small kernels) -> fill
__global__ void k_count(const int2* __restrict__ ei) {
    int e = blockIdx.x * blockDim.x + threadIdx.x;
    if (e >= NE) return;
    atomicAdd(&g_deg[__ldg(&ei[e]).y], 1);
}

__global__ void k_scan1() {    // grid NB, block 1024: per-block exclusive scan
    __shared__ int tmp[1024];
    int tid = threadIdx.x;
    int i = blockIdx.x * 1024 + tid;
    int v = (i < NN) ? g_deg[i] : 0;
    tmp[tid] = v;
    __syncthreads();
    for (int off = 1; off < 1024; off <<= 1) {
        int t = (tid >= off) ? tmp[tid - off] : 0;
        __syncthreads();
        tmp[tid] += t;
        __syncthreads();
    }
    if (i < NN) g_rowstart[i] = tmp[tid] - v;   // exclusive
    if (tid == 1023) g_bsum[blockIdx.x] = tmp[1023];
}

__global__ void k_scan2() {    // 1 block: scan of NB block sums
    if (threadIdx.x == 0) {
        int acc = 0;
        for (int b = 0; b < NB; b++) { int t = g_bsum[b]; g_bsum[b] = acc; acc += t; }
        g_rowstart[NN] = acc;   // == NE
    }
}

__global__ void k_scan3() {    // add block offsets, init cursors
    int i = blockIdx.x * 1024 + threadIdx.x;
    if (i < NN) {
        int r = g_rowstart[i] + g_bsum[blockIdx.x];
        g_rowstart[i] = r;
        g_cursor[i]   = r;
    }
}

__global__ void k_fill(const int2* __restrict__ ei) {
    int e = blockIdx.x * blockDim.x + threadIdx.x;
    if (e >= NE) return;
    int2 sd = __ldg(&ei[e]);
    int pos = atomicAdd(&g_cursor[sd.y], 1);
    g_csr[pos] = make_int2(sd.x, e);
}

// ---------------------------------------------------------------------------
// Fused softmax + aggregation: one warp per dst node.
// loop1: exp(e) per edge (lane-parallel), stash in alpha slot, warp-sum.
// loop2: serial accumulate exp * Wh[src] into register float4 (lane owns 4 of 128).
// loop3: normalize alpha in place (lane-parallel).
__global__ void k_agg(float* __restrict__ out, float* __restrict__ alpha) {
    int warp = threadIdx.x >> 5;
    int lane = threadIdx.x & 31;
    int d = blockIdx.x * 8 + warp;
    if (d >= NN) return;

    int r0 = g_rowstart[d];
    int r1 = g_rowstart[d + 1];
    float4 sd4 = *reinterpret_cast<const float4*>(g_sdst + (size_t)d * 4);

    // loop1: exp + partial sums
    float s0 = 0.f, s1 = 0.f, s2 = 0.f, s3 = 0.f;
    for (int i = r0 + lane; i < r1; i += 32) {
        int2 se = g_csr[i];
        float4 ss = *reinterpret_cast<const float4*>(g_ssrc + (size_t)se.x * 4);
        float v0 = ss.x + sd4.x, v1 = ss.y + sd4.y;
        float v2 = ss.z + sd4.z, v3 = ss.w + sd4.w;
        v0 = v0 > 0.f ? v0 : 0.2f * v0;
        v1 = v1 > 0.f ? v1 : 0.2f * v1;
        v2 = v2 > 0.f ? v2 : 0.2f * v2;
        v3 = v3 > 0.f ? v3 : 0.2f * v3;
        float e0 = __expf(v0), e1 = __expf(v1), e2 = __expf(v2), e3 = __expf(v3);
        reinterpret_cast<float4*>(alpha)[se.y] = make_float4(e0, e1, e2, e3);
        s0 += e0; s1 += e1; s2 += e2; s3 += e3;
    }
#pragma unroll
    for (int o = 16; o; o >>= 1) {
        s0 += __shfl_xor_sync(0xffffffffu, s0, o);
        s1 += __shfl_xor_sync(0xffffffffu, s1, o);
        s2 += __shfl_xor_sync(0xffffffffu, s2, o);
        s3 += __shfl_xor_sync(0xffffffffu, s3, o);
    }
    float i0 = 1.f / (s0 + 1e-9f), i1 = 1.f / (s1 + 1e-9f);
    float i2 = 1.f / (s2 + 1e-9f), i3 = 1.f / (s3 + 1e-9f);

    // make loop1's alpha writes visible to other lanes' loads
    __threadfence_block();
    __syncwarp();

    int h = lane >> 3;
    float invh = (h == 0) ? i0 : (h == 1) ? i1 : (h == 2) ? i2 : i3;

    // loop2: accumulate exp * Wh[src]; normalize once at the end
    const float4* Wh4 = reinterpret_cast<const float4*>(g_Wh);
    float4 acc = make_float4(0.f, 0.f, 0.f, 0.f);
    for (int i = r0; i < r1; i++) {
        int2 se = g_csr[i];                                 // warp-uniform broadcast
        float ex = alpha[(size_t)se.y * 4 + h];             // 4 addrs/warp, broadcast
        float4 wv = Wh4[(size_t)se.x * 32 + lane];
        acc.x = fmaf(ex, wv.x, acc.x);
        acc.y = fmaf(ex, wv.y, acc.y);
        acc.z = fmaf(ex, wv.z, acc.z);
        acc.w = fmaf(ex, wv.w, acc.w);
    }
    acc.x *= invh; acc.y *= invh; acc.z *= invh; acc.w *= invh;
    reinterpret_cast<float4*>(out + (size_t)d * 128)[lane] = acc;

    __syncwarp();

    // loop3: normalize alpha in place
    for (int i = r0 + lane; i < r1; i += 32) {
        int eid = g_csr[i].y;
        float4 a = reinterpret_cast<float4*>(alpha)[eid];
        a.x *= i0; a.y *= i1; a.z *= i2; a.w *= i3;
        reinterpret_cast<float4*>(alpha)[eid] = a;
    }
}

// ---------------------------------------------------------------------------
extern "C" void kernel_launch(void* const* d_in, const int* in_sizes, int n_in,
                              void* d_out, int out_size) {
    const float* x    = (const float*)d_in[0];
    const int2*  ei   = (const int2*)d_in[1];            // [E][2] int32
    const float* W    = (const float*)d_in[2];           // [4][128][32]
    const float* attn = (const float*)d_in[3];           // [4][64]
    float* out   = (float*)d_out;                        // h: [NN][128]
    float* alpha = out + (size_t)NN * 128;               // alpha: [NE][4]

    k_init<<<(NN + 255) / 256, 256>>>();
    k_count<<<(NE + 255) / 256, 256>>>(ei);
    wh_kernel<<<(NN + 3) / 4, 128>>>(x, W, attn);
    k_scan1<<<NB, 1024>>>();
    k_scan2<<<1, 32>>>();
    k_scan3<<<NB, 1024>>>();
    k_fill<<<(NE + 255) / 256, 256>>>(ei);
    k_agg<<<(NN + 7) / 8, 256>>>(out, alpha);
}

// round 14
// speedup vs baseline: 1.5508x; 1.0077x over previous
#include <cuda_runtime.h>

#define NN 50000
#define NE 1600000
#define NB 49          // ceil(NN / 1024)

// ---- scratch (static device globals; no allocation) ----
__device__ float g_Wh[NN * 128];       // [n][h*32+o]
__device__ float g_ssrc[NN * 4];       // per-node src score per head
__device__ float g_sdst[NN * 4];       // per-node dst score per head
__device__ int   g_deg[NN];
__device__ int   g_rowstart[NN + 1];
__device__ int   g_cursor[NN];
__device__ int2  g_csr[NE];            // (src, edge_id) grouped by dst
__device__ int   g_bsum[NB];

// ---------------------------------------------------------------------------
__global__ void k_init() {
    int i = blockIdx.x * blockDim.x + threadIdx.x;
    if (i < NN) g_deg[i] = 0;
}

// ---------------------------------------------------------------------------
// Wh = x @ W per head, fused with per-node score computation. One warp/node.
// Packed f32x2 FMA (Blackwell): halves FMA-pipe issue pressure.
__global__ void wh_kernel(const float* __restrict__ x,
                          const float* __restrict__ W,
                          const float* __restrict__ attn) {
    __shared__ float xs[8][128];
    int warp = threadIdx.x >> 5;
    int lane = threadIdx.x & 31;
    int node = blockIdx.x * 8 + warp;
    if (node >= NN) return;

    float4 xv = reinterpret_cast<const float4*>(x + (size_t)node * 128)[lane];
    reinterpret_cast<float4*>(xs[warp])[lane] = xv;
    __syncwarp();

    int h  = lane >> 3;
    int og = (lane & 7) << 2;
    const float* Wp = W + h * 128 * 32 + og;   // advance 32 floats (128B) per k

    unsigned long long acc01 = 0ull, acc23 = 0ull;   // packed {0.f,0.f}
#pragma unroll 16
    for (int k = 0; k < 128; k++) {
        float xi = xs[warp][k];
        unsigned xiu = __float_as_uint(xi);
        unsigned long long xx;
        asm("mov.b64 %0, {%1, %1};" : "=l"(xx) : "r"(xiu));
        ulonglong2 wv = __ldg(reinterpret_cast<const ulonglong2*>(Wp + k * 32));
        asm("fma.rn.f32x2 %0, %1, %2, %3;" : "=l"(acc01) : "l"(xx), "l"(wv.x), "l"(acc01));
        asm("fma.rn.f32x2 %0, %1, %2, %3;" : "=l"(acc23) : "l"(xx), "l"(wv.y), "l"(acc23));
    }
    float4 acc;
    acc.x = __uint_as_float((unsigned)(acc01 & 0xffffffffu));
    acc.y = __uint_as_float((unsigned)(acc01 >> 32));
    acc.z = __uint_as_float((unsigned)(acc23 & 0xffffffffu));
    acc.w = __uint_as_float((unsigned)(acc23 >> 32));

    reinterpret_cast<float4*>(g_Wh + (size_t)node * 128)[lane] = acc;

    const float* asrc = attn + h * 64 + og;
    const float* adst = asrc + 32;
    float ps = acc.x * asrc[0] + acc.y * asrc[1] + acc.z * asrc[2] + acc.w * asrc[3];
    float pd = acc.x * adst[0] + acc.y * adst[1] + acc.z * adst[2] + acc.w * adst[3];
    ps += __shfl_xor_sync(0xffffffffu, ps, 1);
    ps += __shfl_xor_sync(0xffffffffu, ps, 2);
    ps += __shfl_xor_sync(0xffffffffu, ps, 4);
    pd += __shfl_xor_sync(0xffffffffu, pd, 1);
    pd += __shfl_xor_sync(0xffffffffu, pd, 2);
    pd += __shfl_xor_sync(0xffffffffu, pd, 4);
    if ((lane & 7) == 0) {
        g_ssrc[node * 4 + h] = ps;
        g_sdst[node * 4 + h] = pd;
    }
}

// ---------------------------------------------------------------------------
// CSR build: count -> scan (3 small kernels) -> fill
__global__ void k_count(const int2* __restrict__ ei) {
    int e = blockIdx.x * blockDim.x + threadIdx.x;
    if (e >= NE) return;
    atomicAdd(&g_deg[__ldg(&ei[e]).y], 1);
}

__global__ void k_scan1() {    // grid NB, block 1024: per-block exclusive scan
    __shared__ int tmp[1024];
    int tid = threadIdx.x;
    int i = blockIdx.x * 1024 + tid;
    int v = (i < NN) ? g_deg[i] : 0;
    tmp[tid] = v;
    __syncthreads();
    for (int off = 1; off < 1024; off <<= 1) {
        int t = (tid >= off) ? tmp[tid - off] : 0;
        __syncthreads();
        tmp[tid] += t;
        __syncthreads();
    }
    if (i < NN) g_rowstart[i] = tmp[tid] - v;   // exclusive
    if (tid == 1023) g_bsum[blockIdx.x] = tmp[1023];
}

__global__ void k_scan2() {    // 1 block: scan of NB block sums
    if (threadIdx.x == 0) {
        int acc = 0;
        for (int b = 0; b < NB; b++) { int t = g_bsum[b]; g_bsum[b] = acc; acc += t; }
        g_rowstart[NN] = acc;   // == NE
    }
}

__global__ void k_scan3() {    // add block offsets, init cursors
    int i = blockIdx.x * 1024 + threadIdx.x;
    if (i < NN) {
        int r = g_rowstart[i] + g_bsum[blockIdx.x];
        g_rowstart[i] = r;
        g_cursor[i]   = r;
    }
}

__global__ void k_fill(const int2* __restrict__ ei) {
    int e = blockIdx.x * blockDim.x + threadIdx.x;
    if (e >= NE) return;
    int2 sd = __ldg(&ei[e]);
    int pos = atomicAdd(&g_cursor[sd.y], 1);
    g_csr[pos] = make_int2(sd.x, e);
}

// ---------------------------------------------------------------------------
// Fused softmax + aggregation: one warp per dst node.
__global__ void k_agg(float* __restrict__ out, float* __restrict__ alpha) {
    int warp = threadIdx.x >> 5;
    int lane = threadIdx.x & 31;
    int d = blockIdx.x * 8 + warp;
    if (d >= NN) return;

    int r0 = g_rowstart[d];
    int r1 = g_rowstart[d + 1];
    float4 sd4 = *reinterpret_cast<const float4*>(g_sdst + (size_t)d * 4);

    // loop1: exp + partial sums (lane-parallel)
    float s0 = 0.f, s1 = 0.f, s2 = 0.f, s3 = 0.f;
    for (int i = r0 + lane; i < r1; i += 32) {
        int2 se = g_csr[i];
        float4 ss = *reinterpret_cast<const float4*>(g_ssrc + (size_t)se.x * 4);
        float v0 = ss.x + sd4.x, v1 = ss.y + sd4.y;
        float v2 = ss.z + sd4.z, v3 = ss.w + sd4.w;
        v0 = v0 > 0.f ? v0 : 0.2f * v0;
        v1 = v1 > 0.f ? v1 : 0.2f * v1;
        v2 = v2 > 0.f ? v2 : 0.2f * v2;
        v3 = v3 > 0.f ? v3 : 0.2f * v3;
        float e0 = __expf(v0), e1 = __expf(v1), e2 = __expf(v2), e3 = __expf(v3);
        reinterpret_cast<float4*>(alpha)[se.y] = make_float4(e0, e1, e2, e3);
        s0 += e0; s1 += e1; s2 += e2; s3 += e3;
    }
#pragma unroll
    for (int o = 16; o; o >>= 1) {
        s0 += __shfl_xor_sync(0xffffffffu, s0, o);
        s1 += __shfl_xor_sync(0xffffffffu, s1, o);
        s2 += __shfl_xor_sync(0xffffffffu, s2, o);
        s3 += __shfl_xor_sync(0xffffffffu, s3, o);
    }
    float i0 = 1.f / (s0 + 1e-9f), i1 = 1.f / (s1 + 1e-9f);
    float i2 = 1.f / (s2 + 1e-9f), i3 = 1.f / (s3 + 1e-9f);

    __threadfence_block();
    __syncwarp();

    int h = lane >> 3;
    float invh = (h == 0) ? i0 : (h == 1) ? i1 : (h == 2) ? i2 : i3;

    // loop2: accumulate exp * Wh[src], 4x unrolled for MLP on the L2-hit path
    const float4* Wh4 = reinterpret_cast<const float4*>(g_Wh);
    float4 acc = make_float4(0.f, 0.f, 0.f, 0.f);
    int i = r0;
    for (; i + 4 <= r1; i += 4) {
        int2 c0 = g_csr[i], c1 = g_csr[i + 1], c2 = g_csr[i + 2], c3 = g_csr[i + 3];
        float e0 = alpha[(size_t)c0.y * 4 + h];
        float e1 = alpha[(size_t)c1.y * 4 + h];
        float e2 = alpha[(size_t)c2.y * 4 + h];
        float e3 = alpha[(size_t)c3.y * 4 + h];
        float4 w0 = __ldg(&Wh4[(size_t)c0.x * 32 + lane]);
        float4 w1 = __ldg(&Wh4[(size_t)c1.x * 32 + lane]);
        float4 w2 = __ldg(&Wh4[(size_t)c2.x * 32 + lane]);
        float4 w3 = __ldg(&Wh4[(size_t)c3.x * 32 + lane]);
        acc.x = fmaf(e0, w0.x, acc.x); acc.y = fmaf(e0, w0.y, acc.y);
        acc.z = fmaf(e0, w0.z, acc.z); acc.w = fmaf(e0, w0.w, acc.w);
        acc.x = fmaf(e1, w1.x, acc.x); acc.y = fmaf(e1, w1.y, acc.y);
        acc.z = fmaf(e1, w1.z, acc.z); acc.w = fmaf(e1, w1.w, acc.w);
        acc.x = fmaf(e2, w2.x, acc.x); acc.y = fmaf(e2, w2.y, acc.y);
        acc.z = fmaf(e2, w2.z, acc.z); acc.w = fmaf(e2, w2.w, acc.w);
        acc.x = fmaf(e3, w3.x, acc.x); acc.y = fmaf(e3, w3.y, acc.y);
        acc.z = fmaf(e3, w3.z, acc.z); acc.w = fmaf(e3, w3.w, acc.w);
    }
    for (; i < r1; i++) {
        int2 se = g_csr[i];
        float ex = alpha[(size_t)se.y * 4 + h];
        float4 wv = __ldg(&Wh4[(size_t)se.x * 32 + lane]);
        acc.x = fmaf(ex, wv.x, acc.x);
        acc.y = fmaf(ex, wv.y, acc.y);
        acc.z = fmaf(ex, wv.z, acc.z);
        acc.w = fmaf(ex, wv.w, acc.w);
    }
    acc.x *= invh; acc.y *= invh; acc.z *= invh; acc.w *= invh;
    reinterpret_cast<float4*>(out + (size_t)d * 128)[lane] = acc;

    __syncwarp();

    // loop3: normalize alpha in place (lane-parallel)
    for (int i2_ = r0 + lane; i2_ < r1; i2_ += 32) {
        int eid = g_csr[i2_].y;
        float4 a = reinterpret_cast<float4*>(alpha)[eid];
        a.x *= i0; a.y *= i1; a.z *= i2; a.w *= i3;
        reinterpret_cast<float4*>(alpha)[eid] = a;
    }
}

// ---------------------------------------------------------------------------
extern "C" void kernel_launch(void* const* d_in, const int* in_sizes, int n_in,
                              void* d_out, int out_size) {
    const float* x    = (const float*)d_in[0];
    const int2*  ei   = (const int2*)d_in[1];            // [E][2] int32
    const float* W    = (const float*)d_in[2];           // [4][128][32]
    const float* attn = (const float*)d_in[3];           // [4][64]
    float* out   = (float*)d_out;                        // h: [NN][128]
    float* alpha = out + (size_t)NN * 128;               // alpha: [NE][4]

    k_init<<<(NN + 255) / 256, 256>>>();
    k_count<<<(NE + 255) / 256, 256>>>(ei);
    wh_kernel<<<(NN + 7) / 8, 256>>>(x, W, attn);
    k_scan1<<<NB, 1024>>>();
    k_scan2<<<1, 32>>>();
    k_scan3<<<NB, 1024>>>();
    k_fill<<<(NE + 255) / 256, 256>>>(ei);
    k_agg<<<(NN + 7) / 8, 256>>>(out, alpha);
}

// round 16
// speedup vs baseline: 1.8296x; 1.1798x over previous
#include <cuda_runtime.h>

#define NN 50000
#define NE 1600000
#define NB 49          // ceil(NN / 1024)
#define CB 6250        // count blocks = (NE+255)/256 ; also wh blocks = (NN+7)/8
#define MAXC 128       // per-warp smem exp-cache capacity (edges)

// ---- scratch (static device globals; no allocation) ----
__device__ float g_Wh[NN * 128];       // [n][h*32+o]
__device__ float g_ssrc[NN * 4];       // per-node src score per head
__device__ float g_sdst[NN * 4];       // per-node dst score per head
__device__ int   g_deg[NN];            // BSS-zero at load; re-zeroed by k_scan3
__device__ int   g_rowstart[NN + 1];
__device__ int   g_cursor[NN];
__device__ int2  g_csr[NE];            // (src, edge_id) grouped by dst
__device__ int   g_bsum[NB];

// ---------------------------------------------------------------------------
// Merged kernel: blocks [0,CB) count dst degrees; blocks [CB,2CB) compute
// Wh = x @ W fused with per-node attention scores (one warp per node).
__global__ void k_count_wh(const float* __restrict__ x,
                           const float* __restrict__ W,
                           const float* __restrict__ attn,
                           const int2* __restrict__ ei) {
    __shared__ float xs[8][128];

    if (blockIdx.x < CB) {            // ---- degree count part ----
        int e = blockIdx.x * 256 + threadIdx.x;
        if (e < NE) atomicAdd(&g_deg[__ldg(&ei[e]).y], 1);
        return;
    }

    // ---- Wh + scores part ----
    int warp = threadIdx.x >> 5;
    int lane = threadIdx.x & 31;
    int node = (blockIdx.x - CB) * 8 + warp;
    if (node >= NN) return;

    float4 xv = reinterpret_cast<const float4*>(x + (size_t)node * 128)[lane];
    reinterpret_cast<float4*>(xs[warp])[lane] = xv;
    __syncwarp();

    int h  = lane >> 3;
    int og = (lane & 7) << 2;
    const float* Wp = W + h * 128 * 32 + og;

    unsigned long long acc01 = 0ull, acc23 = 0ull;   // packed {0,0}
#pragma unroll 16
    for (int k = 0; k < 128; k++) {
        float xi = xs[warp][k];
        unsigned xiu = __float_as_uint(xi);
        unsigned long long xx;
        asm("mov.b64 %0, {%1, %1};" : "=l"(xx) : "r"(xiu));
        ulonglong2 wv = __ldg(reinterpret_cast<const ulonglong2*>(Wp + k * 32));
        asm("fma.rn.f32x2 %0, %1, %2, %3;" : "=l"(acc01) : "l"(xx), "l"(wv.x), "l"(acc01));
        asm("fma.rn.f32x2 %0, %1, %2, %3;" : "=l"(acc23) : "l"(xx), "l"(wv.y), "l"(acc23));
    }
    float4 acc;
    acc.x = __uint_as_float((unsigned)(acc01 & 0xffffffffu));
    acc.y = __uint_as_float((unsigned)(acc01 >> 32));
    acc.z = __uint_as_float((unsigned)(acc23 & 0xffffffffu));
    acc.w = __uint_as_float((unsigned)(acc23 >> 32));

    reinterpret_cast<float4*>(g_Wh + (size_t)node * 128)[lane] = acc;

    const float* asrc = attn + h * 64 + og;
    const float* adst = asrc + 32;
    float ps = acc.x * asrc[0] + acc.y * asrc[1] + acc.z * asrc[2] + acc.w * asrc[3];
    float pd = acc.x * adst[0] + acc.y * adst[1] + acc.z * adst[2] + acc.w * adst[3];
    ps += __shfl_xor_sync(0xffffffffu, ps, 1);
    ps += __shfl_xor_sync(0xffffffffu, ps, 2);
    ps += __shfl_xor_sync(0xffffffffu, ps, 4);
    pd += __shfl_xor_sync(0xffffffffu, pd, 1);
    pd += __shfl_xor_sync(0xffffffffu, pd, 2);
    pd += __shfl_xor_sync(0xffffffffu, pd, 4);
    if ((lane & 7) == 0) {
        g_ssrc[node * 4 + h] = ps;
        g_sdst[node * 4 + h] = pd;
    }
}

// ---------------------------------------------------------------------------
__global__ void k_scan1() {    // grid NB, block 1024: per-block exclusive scan
    __shared__ int tmp[1024];
    int tid = threadIdx.x;
    int i = blockIdx.x * 1024 + tid;
    int v = (i < NN) ? g_deg[i] : 0;
    tmp[tid] = v;
    __syncthreads();
    for (int off = 1; off < 1024; off <<= 1) {
        int t = (tid >= off) ? tmp[tid - off] : 0;
        __syncthreads();
        tmp[tid] += t;
        __syncthreads();
    }
    if (i < NN) g_rowstart[i] = tmp[tid] - v;   // exclusive
    if (tid == 1023) g_bsum[blockIdx.x] = tmp[1023];
}

__global__ void k_scan2() {    // 1 block: scan of NB block sums
    if (threadIdx.x == 0) {
        int acc = 0;
        for (int b = 0; b < NB; b++) { int t = g_bsum[b]; g_bsum[b] = acc; acc += t; }
        g_rowstart[NN] = acc;   // == NE
    }
}

__global__ void k_scan3() {    // add block offsets, init cursors, re-zero deg
    int i = blockIdx.x * 1024 + threadIdx.x;
    if (i < NN) {
        int r = g_rowstart[i] + g_bsum[blockIdx.x];
        g_rowstart[i] = r;
        g_cursor[i]   = r;
        g_deg[i]      = 0;     // ready for next graph replay (deg dead after scan1)
    }
}

__global__ void k_fill(const int2* __restrict__ ei) {
    int e = blockIdx.x * blockDim.x + threadIdx.x;
    if (e >= NE) return;
    int2 sd = __ldg(&ei[e]);
    int pos = atomicAdd(&g_cursor[sd.y], 1);
    g_csr[pos] = make_int2(sd.x, e);
}

// ---------------------------------------------------------------------------
// Fused softmax + aggregation: one warp per dst node, smem exp cache.
__global__ void k_agg(float* __restrict__ out, float* __restrict__ alpha) {
    __shared__ float exps[8][MAXC * 4];
    int warp = threadIdx.x >> 5;
    int lane = threadIdx.x & 31;
    int d = blockIdx.x * 8 + warp;
    if (d >= NN) return;

    int r0 = g_rowstart[d];
    int r1 = g_rowstart[d + 1];
    int deg = r1 - r0;
    int ncache = deg < MAXC ? deg : MAXC;
    float4 sd4 = *reinterpret_cast<const float4*>(g_sdst + (size_t)d * 4);

    // loop1: exp per edge (lane-parallel) -> smem cache (+ global for overflow)
    float s0 = 0.f, s1 = 0.f, s2 = 0.f, s3 = 0.f;
    for (int j = lane; j < deg; j += 32) {
        int2 se = g_csr[r0 + j];
        float4 ss = *reinterpret_cast<const float4*>(g_ssrc + (size_t)se.x * 4);
        float v0 = ss.x + sd4.x, v1 = ss.y + sd4.y;
        float v2 = ss.z + sd4.z, v3 = ss.w + sd4.w;
        v0 = v0 > 0.f ? v0 : 0.2f * v0;
        v1 = v1 > 0.f ? v1 : 0.2f * v1;
        v2 = v2 > 0.f ? v2 : 0.2f * v2;
        v3 = v3 > 0.f ? v3 : 0.2f * v3;
        float4 ex = make_float4(__expf(v0), __expf(v1), __expf(v2), __expf(v3));
        if (j < MAXC) *reinterpret_cast<float4*>(&exps[warp][j * 4]) = ex;
        else          reinterpret_cast<float4*>(alpha)[se.y] = ex;   // rare overflow
        s0 += ex.x; s1 += ex.y; s2 += ex.z; s3 += ex.w;
    }
#pragma unroll
    for (int o = 16; o; o >>= 1) {
        s0 += __shfl_xor_sync(0xffffffffu, s0, o);
        s1 += __shfl_xor_sync(0xffffffffu, s1, o);
        s2 += __shfl_xor_sync(0xffffffffu, s2, o);
        s3 += __shfl_xor_sync(0xffffffffu, s3, o);
    }
    float i0 = 1.f / (s0 + 1e-9f), i1 = 1.f / (s1 + 1e-9f);
    float i2 = 1.f / (s2 + 1e-9f), i3 = 1.f / (s3 + 1e-9f);

    __syncwarp();
    if (deg > MAXC) __threadfence_block();   // warp-uniform; overflow global reads

    int h = lane >> 3;
    float invh = (h == 0) ? i0 : (h == 1) ? i1 : (h == 2) ? i2 : i3;

    // loop2: accumulate exp * Wh[src]; exp from smem (broadcast, conflict-free)
    const float4* Wh4 = reinterpret_cast<const float4*>(g_Wh);
    float4 acc = make_float4(0.f, 0.f, 0.f, 0.f);
    int j = 0;
    for (; j + 4 <= ncache; j += 4) {
        int2 c0 = g_csr[r0 + j], c1 = g_csr[r0 + j + 1];
        int2 c2 = g_csr[r0 + j + 2], c3 = g_csr[r0 + j + 3];
        float e0 = exps[warp][(j + 0) * 4 + h];
        float e1 = exps[warp][(j + 1) * 4 + h];
        float e2 = exps[warp][(j + 2) * 4 + h];
        float e3 = exps[warp][(j + 3) * 4 + h];
        float4 w0 = __ldg(&Wh4[(size_t)c0.x * 32 + lane]);
        float4 w1 = __ldg(&Wh4[(size_t)c1.x * 32 + lane]);
        float4 w2 = __ldg(&Wh4[(size_t)c2.x * 32 + lane]);
        float4 w3 = __ldg(&Wh4[(size_t)c3.x * 32 + lane]);
        acc.x = fmaf(e0, w0.x, acc.x); acc.y = fmaf(e0, w0.y, acc.y);
        acc.z = fmaf(e0, w0.z, acc.z); acc.w = fmaf(e0, w0.w, acc.w);
        acc.x = fmaf(e1, w1.x, acc.x); acc.y = fmaf(e1, w1.y, acc.y);
        acc.z = fmaf(e1, w1.z, acc.z); acc.w = fmaf(e1, w1.w, acc.w);
        acc.x = fmaf(e2, w2.x, acc.x); acc.y = fmaf(e2, w2.y, acc.y);
        acc.z = fmaf(e2, w2.z, acc.z); acc.w = fmaf(e2, w2.w, acc.w);
        acc.x = fmaf(e3, w3.x, acc.x); acc.y = fmaf(e3, w3.y, acc.y);
        acc.z = fmaf(e3, w3.z, acc.z); acc.w = fmaf(e3, w3.w, acc.w);
    }
    for (; j < ncache; j++) {
        int2 se = g_csr[r0 + j];
        float ex = exps[warp][j * 4 + h];
        float4 wv = __ldg(&Wh4[(size_t)se.x * 32 + lane]);
        acc.x = fmaf(ex, wv.x, acc.x);
        acc.y = fmaf(ex, wv.y, acc.y);
        acc.z = fmaf(ex, wv.z, acc.z);
        acc.w = fmaf(ex, wv.w, acc.w);
    }
    for (; j < deg; j++) {                      // overflow: exp from global
        int2 se = g_csr[r0 + j];
        float ex = alpha[(size_t)se.y * 4 + h];
        float4 wv = __ldg(&Wh4[(size_t)se.x * 32 + lane]);
        acc.x = fmaf(ex, wv.x, acc.x);
        acc.y = fmaf(ex, wv.y, acc.y);
        acc.z = fmaf(ex, wv.z, acc.z);
        acc.w = fmaf(ex, wv.w, acc.w);
    }
    acc.x *= invh; acc.y *= invh; acc.z *= invh; acc.w *= invh;
    reinterpret_cast<float4*>(out + (size_t)d * 128)[lane] = acc;

    // loop3: write final normalized alpha (single global write per edge)
    for (int jj = lane; jj < deg; jj += 32) {
        int eid = g_csr[r0 + jj].y;
        float4 a = (jj < MAXC) ? *reinterpret_cast<float4*>(&exps[warp][jj * 4])
                               : reinterpret_cast<float4*>(alpha)[eid];
        a.x *= i0; a.y *= i1; a.z *= i2; a.w *= i3;
        reinterpret_cast<float4*>(alpha)[eid] = a;
    }
}

// ---------------------------------------------------------------------------
extern "C" void kernel_launch(void* const* d_in, const int* in_sizes, int n_in,
                              void* d_out, int out_size) {
    const float* x    = (const float*)d_in[0];
    const int2*  ei   = (const int2*)d_in[1];            // [E][2] int32
    const float* W    = (const float*)d_in[2];           // [4][128][32]
    const float* attn = (const float*)d_in[3];           // [4][64]
    float* out   = (float*)d_out;                        // h: [NN][128]
    float* alpha = out + (size_t)NN * 128;               // alpha: [NE][4]

    k_count_wh<<<2 * CB, 256>>>(x, W, attn, ei);
    k_scan1<<<NB, 1024>>>();
    k_scan2<<<1, 32>>>();
    k_scan3<<<NB, 1024>>>();
    k_fill<<<(NE + 255) / 256, 256>>>(ei);
    k_agg<<<(NN + 7) / 8, 256>>>(out, alpha);
}